// round 16
// baseline (speedup 1.0000x reference)
#include <cuda_runtime.h>
#include <cuda_bf16.h>
#include <math.h>

#define T_ 128
#define B_ 128
#define I_ 256
#define H_ 256
#define G4_ 1024

typedef unsigned long long u64;
typedef unsigned int u32;

__device__ float g_preact[(size_t)T_ * B_ * G4_];

__device__ __forceinline__ u32 smem_u32(const void* p) {
    u32 a;
    asm("{ .reg .u64 t; cvta.to.shared.u64 t, %1; cvt.u32.u64 %0, t; }"
        : "=r"(a) : "l"(p));
    return a;
}
__device__ __forceinline__ float fast_sig(float x) {
    return __fdividef(1.f, 1.f + __expf(-x));
}
__device__ __forceinline__ float fast_tanh(float x) {
    float a = fminf(fabsf(x), 15.f);
    float e = __expf(2.f * a);
    float r = 1.f - __fdividef(2.f, e + 1.f);
    return copysignf(r, x);
}
__device__ __forceinline__ u32 pack_bf16x2(float lo, float hi) {
    __nv_bfloat162 v = __halves2bfloat162(__float2bfloat16(lo), __float2bfloat16(hi));
    u32 r;
    memcpy(&r, &v, 4);
    return r;
}

// ------------------------- Phase 1 (verbatim, ~165us) ----------------------
__global__ __launch_bounds__(256) void lstm_phase1(
    const float* __restrict__ x, const float* __restrict__ Wi,
    const float* __restrict__ bi, const float* __restrict__ bh,
    float* __restrict__ preact)
{
    __shared__ float As[2][16][128];
    __shared__ float Bs[2][16][128];

    const int t = blockIdx.y, n0 = blockIdx.x * 128, tid = threadIdx.x;
    const int tx = tid & 15, ty = tid >> 4;
    const float* xA = x + (size_t)t * (B_ * I_);
    const float* WB = Wi + (size_t)t * (I_ * G4_) + n0;
    const int am = tid >> 1, aq = (tid & 1) * 2;
    const int bk = tid >> 4, bn = (tid & 15) * 4;

    u64 acc2[8][4];
#pragma unroll
    for (int i = 0; i < 8; ++i)
#pragma unroll
        for (int j = 0; j < 4; ++j) acc2[i][j] = 0ULL;

    {
        float4 a0 = *(const float4*)(xA + am * I_ + (aq + 0) * 4);
        float4 a1 = *(const float4*)(xA + am * I_ + (aq + 1) * 4);
        As[0][aq * 4 + 0][am] = a0.x; As[0][aq * 4 + 1][am] = a0.y;
        As[0][aq * 4 + 2][am] = a0.z; As[0][aq * 4 + 3][am] = a0.w;
        As[0][aq * 4 + 4][am] = a1.x; As[0][aq * 4 + 5][am] = a1.y;
        As[0][aq * 4 + 6][am] = a1.z; As[0][aq * 4 + 7][am] = a1.w;
        *(float4*)&Bs[0][bk][bn]      = *(const float4*)(WB + (size_t)bk * G4_ + bn);
        *(float4*)&Bs[0][bk][bn + 64] = *(const float4*)(WB + (size_t)bk * G4_ + bn + 64);
    }
    __syncthreads();

    for (int kt = 0; kt < 16; ++kt) {
        const int cur = kt & 1;
        float4 pa0, pa1, pb0, pb1;
        if (kt < 15) {
            const int k0 = (kt + 1) * 16;
            pa0 = *(const float4*)(xA + am * I_ + k0 + (aq + 0) * 4);
            pa1 = *(const float4*)(xA + am * I_ + k0 + (aq + 1) * 4);
            pb0 = *(const float4*)(WB + (size_t)(k0 + bk) * G4_ + bn);
            pb1 = *(const float4*)(WB + (size_t)(k0 + bk) * G4_ + bn + 64);
        }
#pragma unroll
        for (int kk = 0; kk < 16; ++kk) {
            float4 a0 = *(float4*)&As[cur][kk][ty * 4];
            float4 a1 = *(float4*)&As[cur][kk][64 + ty * 4];
            ulonglong2 bp0 = *(ulonglong2*)&Bs[cur][kk][tx * 4];
            ulonglong2 bp1 = *(ulonglong2*)&Bs[cur][kk][64 + tx * 4];
            float av[8] = {a0.x, a0.y, a0.z, a0.w, a1.x, a1.y, a1.z, a1.w};
#pragma unroll
            for (int i = 0; i < 8; ++i) {
                u64 ad;
                asm("mov.b64 %0, {%1, %1};" : "=l"(ad) : "f"(av[i]));
                asm("fma.rn.f32x2 %0, %1, %2, %0;" : "+l"(acc2[i][0]) : "l"(ad), "l"(bp0.x));
                asm("fma.rn.f32x2 %0, %1, %2, %0;" : "+l"(acc2[i][1]) : "l"(ad), "l"(bp0.y));
                asm("fma.rn.f32x2 %0, %1, %2, %0;" : "+l"(acc2[i][2]) : "l"(ad), "l"(bp1.x));
                asm("fma.rn.f32x2 %0, %1, %2, %0;" : "+l"(acc2[i][3]) : "l"(ad), "l"(bp1.y));
            }
        }
        if (kt < 15) {
            const int nb = cur ^ 1;
            As[nb][aq * 4 + 0][am] = pa0.x; As[nb][aq * 4 + 1][am] = pa0.y;
            As[nb][aq * 4 + 2][am] = pa0.z; As[nb][aq * 4 + 3][am] = pa0.w;
            As[nb][aq * 4 + 4][am] = pa1.x; As[nb][aq * 4 + 5][am] = pa1.y;
            As[nb][aq * 4 + 6][am] = pa1.z; As[nb][aq * 4 + 7][am] = pa1.w;
            *(float4*)&Bs[nb][bk][bn]      = pb0;
            *(float4*)&Bs[nb][bk][bn + 64] = pb1;
            __syncthreads();
        }
    }

    const float* bip = bi + (size_t)t * G4_ + n0;
    const float* bhp = bh + (size_t)t * G4_ + n0;
    float* Cp = preact + (size_t)t * (B_ * G4_) + n0;
    float4 i0 = *(const float4*)(bip + tx * 4);
    float4 h0 = *(const float4*)(bhp + tx * 4);
    float4 i1 = *(const float4*)(bip + 64 + tx * 4);
    float4 h1 = *(const float4*)(bhp + 64 + tx * 4);
    float bs[8] = {i0.x + h0.x, i0.y + h0.y, i0.z + h0.z, i0.w + h0.w,
                   i1.x + h1.x, i1.y + h1.y, i1.z + h1.z, i1.w + h1.w};
#pragma unroll
    for (int i = 0; i < 8; ++i) {
        const int m = (i < 4) ? (ty * 4 + i) : (64 + ty * 4 + (i - 4));
        float a[8];
#pragma unroll
        for (int j = 0; j < 4; ++j)
            asm("mov.b64 {%0, %1}, %2;" : "=f"(a[j * 2]), "=f"(a[j * 2 + 1]) : "l"(acc2[i][j]));
        float4 v0 = make_float4(a[0] + bs[0], a[1] + bs[1], a[2] + bs[2], a[3] + bs[3]);
        float4 v1 = make_float4(a[4] + bs[4], a[5] + bs[5], a[6] + bs[6], a[7] + bs[7]);
        *(float4*)(Cp + (size_t)m * G4_ + tx * 4)      = v0;
        *(float4*)(Cp + (size_t)m * G4_ + 64 + tx * 4) = v1;
    }
}

// ------------------------- Cluster DSMEM scan -------------------------------
// 32 CTAs, clusters of 8 = one row group (32 rows). CTA rank ci owns hcols
// [32ci, 32ci+32) -> 128 gathered gate cols. h handoff via st.shared::cluster
// into peers' double-buffered Hs; one cluster barrier per step.
#define ROWB 528                       // 264 bf16 per Hs/Ws row
#define HS_PLANE (32 * ROWB)           // 16896
#define HS_BUF   (2 * HS_PLANE)        // 33792 (hi+lo)
#define OFF_HS   0                     // [2 buf][2 plane][32][528]
#define OFF_WS   (2 * HS_BUF)          // 67584: [2 plane][128][528]
#define WS_PLANE (128 * ROWB)          // 67584
#define OFF_GSM  (OFF_WS + 2 * WS_PLANE)   // 202752: float[32][132]
#define SM_TOT   (OFF_GSM + 32 * 132 * 4)  // 219648

#define MMA_BF16(d0,d1,d2,d3,a0,a1,a2,a3,b0,b1)                              \
    asm volatile("mma.sync.aligned.m16n8k16.row.col.f32.bf16.bf16.f32 "      \
        "{%0,%1,%2,%3}, {%4,%5,%6,%7}, {%8,%9}, {%0,%1,%2,%3};"              \
        : "+f"(d0), "+f"(d1), "+f"(d2), "+f"(d3)                             \
        : "r"(a0), "r"(a1), "r"(a2), "r"(a3), "r"(b0), "r"(b1))

__global__ __launch_bounds__(256, 1) __cluster_dims__(8, 1, 1)
void lstm_scan_cl(
    const float* __restrict__ h0, const float* __restrict__ c0,
    const float* __restrict__ Wh, const float* __restrict__ pre,
    float* __restrict__ outputs, float* __restrict__ hfin, float* __restrict__ cfin)
{
    extern __shared__ char smc[];
    const u32 sb = smem_u32(smc);
    float* gsm = (float*)(smc + OFF_GSM);

    const int tid = threadIdx.x;
    u32 ci;
    asm("mov.u32 %0, %%cluster_ctarank;" : "=r"(ci));
    const int rg = blockIdx.x >> 3;          // cluster id = row group
    const int r0 = rg * 32;
    const int hc0 = (int)ci * 32;            // this CTA's h-col slice base

    // MMA mapping
    const int wid = tid >> 5, lane = tid & 31;
    const int mtile = wid & 1, nblk = wid >> 1;          // 2 m-tiles, 4 n-blocks
    const u32 a_off = (u32)((mtile * 16 + (lane & 15)) * ROWB + (lane >> 4) * 16);
    const u32 b_base = (u32)((lane & 7) * ROWB + ((lane >> 3) & 1) * 16);

    // epilogue mapping: thread -> (row r, cols c4..c4+3 of this CTA's slice)
    const int r  = tid >> 3;
    const int c4 = (tid & 7) * 4;

    float creg[4];
    {
        float4 cv = *(const float4*)(c0 + (size_t)(r0 + r) * H_ + hc0 + c4);
        creg[0] = cv.x; creg[1] = cv.y; creg[2] = cv.z; creg[3] = cv.w;
    }

    // prologue: fill Hs[0] (full 32 rows x 256 cols) from h0, bf16 hi/lo
    {
        const int rr = tid >> 3;
        const int kb = (tid & 7) * 32;
        const float2* src = (const float2*)(h0 + (size_t)(r0 + rr) * H_ + kb);
        u32* dhi = (u32*)(smc + OFF_HS + rr * ROWB + kb * 2);
        u32* dlo = (u32*)((char*)dhi + HS_PLANE);
#pragma unroll
        for (int j = 0; j < 16; ++j) {
            float2 v = src[j];
            __nv_bfloat16 b0 = __float2bfloat16(v.x);
            __nv_bfloat16 b1 = __float2bfloat16(v.y);
            u32 hw;
            {
                __nv_bfloat162 p2 = __halves2bfloat162(b0, b1);
                memcpy(&hw, &p2, 4);
            }
            dhi[j] = hw;
            dlo[j] = pack_bf16x2(v.x - __bfloat162float(b0),
                                 v.y - __bfloat162float(b1));
        }
    }

    for (int t = 0; t < T_; ++t) {
        const int buf = t & 1;

        // ---- Ws fill for step t (h-independent): 128 gathered cols x 256 k
        {
            const float* Wt = Wh + (size_t)t * H_ * G4_;
#pragma unroll
            for (int i = 0; i < 16; ++i) {
                const int s = i * 256 + tid;
                const int k0 = (s >> 5) * 2;         // even k
                const int q = s & 31;
                const int gc4 = q * 4;               // gathered col group
                const int g = q >> 3, c = (q & 7) * 4;
                const int n = g * 256 + hc0 + c;
                float4 v0 = __ldg((const float4*)(Wt + (size_t)k0 * G4_ + n));
                float4 v1 = __ldg((const float4*)(Wt + (size_t)(k0 + 1) * G4_ + n));
                const float f0[4] = {v0.x, v0.y, v0.z, v0.w};
                const float f1[4] = {v1.x, v1.y, v1.z, v1.w};
#pragma unroll
                for (int j = 0; j < 4; ++j) {
                    __nv_bfloat16 h0b = __float2bfloat16(f0[j]);
                    __nv_bfloat16 h1b = __float2bfloat16(f1[j]);
                    u32 hw;
                    {
                        __nv_bfloat162 p2 = __halves2bfloat162(h0b, h1b);
                        memcpy(&hw, &p2, 4);
                    }
                    u32 lw = pack_bf16x2(f0[j] - __bfloat162float(h0b),
                                         f1[j] - __bfloat162float(h1b));
                    const u32 off = (u32)(gc4 + j) * ROWB + (u32)k0 * 2;
                    *(u32*)(smc + OFF_WS + off)            = hw;
                    *(u32*)(smc + OFF_WS + WS_PLANE + off) = lw;
                }
            }
        }

        // ---- pre prefetch: 16 gate scalars (4 cells x 4 gates)
        float4 pv[4];
        {
            const float* pt = pre + (size_t)t * B_ * G4_ + (size_t)(r0 + r) * G4_;
#pragma unroll
            for (int g = 0; g < 4; ++g)
                pv[g] = __ldg((const float4*)(pt + g * 256 + hc0 + c4));
        }

        // ---- wait for peers' h[t-1] DSMEM writes (pairs arrive of step t-1)
        if (t > 0)
            asm volatile("barrier.cluster.wait.aligned;" ::: "memory");
        __syncthreads();   // Ws (and prologue Hs at t=0) visible CTA-wide

        // ---- HMMA: D[32x128] = HsHi@WsHi + HsHi@WsLo + HsLo@WsHi, K=256
        float d[4][4];
#pragma unroll
        for (int j = 0; j < 4; ++j) { d[j][0] = d[j][1] = d[j][2] = d[j][3] = 0.f; }
        {
            const u32 abase = sb + OFF_HS + (u32)buf * HS_BUF + a_off;
            const u32 bbase = sb + OFF_WS + b_base;
#pragma unroll
            for (int kt = 0; kt < 16; ++kt) {
                const u32 ab = abase + kt * 32;
                u32 ah0, ah1, ah2, ah3, al0, al1, al2, al3;
                asm volatile("ldmatrix.sync.aligned.m8n8.x4.shared.b16 {%0,%1,%2,%3}, [%4];"
                    : "=r"(ah0), "=r"(ah1), "=r"(ah2), "=r"(ah3) : "r"(ab));
                asm volatile("ldmatrix.sync.aligned.m8n8.x4.shared.b16 {%0,%1,%2,%3}, [%4];"
                    : "=r"(al0), "=r"(al1), "=r"(al2), "=r"(al3) : "r"(ab + HS_PLANE));
#pragma unroll
                for (int j = 0; j < 4; ++j) {
                    const int nt = nblk * 4 + j;
                    const u32 bb = bbase + (u32)nt * 8 * ROWB + kt * 32;
                    u32 bh0, bh1, bl0, bl1;
                    asm volatile("ldmatrix.sync.aligned.m8n8.x2.shared.b16 {%0,%1}, [%2];"
                        : "=r"(bh0), "=r"(bh1) : "r"(bb));
                    asm volatile("ldmatrix.sync.aligned.m8n8.x2.shared.b16 {%0,%1}, [%2];"
                        : "=r"(bl0), "=r"(bl1) : "r"(bb + WS_PLANE));
                    MMA_BF16(d[j][0], d[j][1], d[j][2], d[j][3], ah0, ah1, ah2, ah3, bh0, bh1);
                    MMA_BF16(d[j][0], d[j][1], d[j][2], d[j][3], ah0, ah1, ah2, ah3, bl0, bl1);
                    MMA_BF16(d[j][0], d[j][1], d[j][2], d[j][3], al0, al1, al2, al3, bh0, bh1);
                }
            }
        }
        // store D fragments to gsm
#pragma unroll
        for (int j = 0; j < 4; ++j) {
            const int nt = nblk * 4 + j;
            const int m = mtile * 16 + (lane >> 2);
            const int n = nt * 8 + (lane & 3) * 2;
            *(float2*)&gsm[m * 132 + n]       = make_float2(d[j][0], d[j][1]);
            *(float2*)&gsm[(m + 8) * 132 + n] = make_float2(d[j][2], d[j][3]);
        }
        __syncthreads();

        // ---- fused cell update (4 cells: row r, cols c4..c4+3)
        float h4[4];
#pragma unroll
        for (int j = 0; j < 4; ++j) {
            const float gi = gsm[r * 132 +   0 + c4 + j] + pv[0].x * 0.f +
                             ((const float*)&pv[0])[j];
            const float gf = gsm[r * 132 +  32 + c4 + j] + ((const float*)&pv[1])[j];
            const float go = gsm[r * 132 +  64 + c4 + j] + ((const float*)&pv[2])[j];
            const float gc = gsm[r * 132 +  96 + c4 + j] + ((const float*)&pv[3])[j];
            const float ig = fast_sig(gi);
            const float fg = fast_sig(gf);
            const float og = fast_sig(go);
            const float gt = fast_tanh(gc);
            creg[j] = fg * creg[j] + ig * gt;
            h4[j] = og * fast_tanh(creg[j]);
        }
        *(float4*)(outputs + (size_t)t * B_ * H_ + (size_t)(r0 + r) * H_ + hc0 + c4) =
            make_float4(h4[0], h4[1], h4[2], h4[3]);

        if (t < T_ - 1) {
            // ---- publish h[t] into all 8 cluster CTAs' Hs[buf^1] via DSMEM
            __nv_bfloat16 e0 = __float2bfloat16(h4[0]);
            __nv_bfloat16 e1 = __float2bfloat16(h4[1]);
            __nv_bfloat16 e2 = __float2bfloat16(h4[2]);
            __nv_bfloat16 e3 = __float2bfloat16(h4[3]);
            u32 hw0, hw1;
            {
                __nv_bfloat162 p0 = __halves2bfloat162(e0, e1);
                __nv_bfloat162 p1 = __halves2bfloat162(e2, e3);
                memcpy(&hw0, &p0, 4);
                memcpy(&hw1, &p1, 4);
            }
            const u32 lw0 = pack_bf16x2(h4[0] - __bfloat162float(e0),
                                        h4[1] - __bfloat162float(e1));
            const u32 lw1 = pack_bf16x2(h4[2] - __bfloat162float(e2),
                                        h4[3] - __bfloat162float(e3));
            const u64 hiv = ((u64)hw1 << 32) | hw0;
            const u64 lov = ((u64)lw1 << 32) | lw0;
            const u32 la_hi = sb + OFF_HS + (u32)(buf ^ 1) * HS_BUF +
                              (u32)r * ROWB + (u32)(hc0 + c4) * 2;
            const u32 la_lo = la_hi + HS_PLANE;
#pragma unroll
            for (int q = 0; q < 8; ++q) {
                u32 ra;
                asm volatile("mapa.shared::cluster.u32 %0, %1, %2;"
                             : "=r"(ra) : "r"(la_hi), "r"(q));
                asm volatile("st.shared::cluster.u64 [%0], %1;"
                             :: "r"(ra), "l"(hiv) : "memory");
                asm volatile("mapa.shared::cluster.u32 %0, %1, %2;"
                             : "=r"(ra) : "r"(la_lo), "r"(q));
                asm volatile("st.shared::cluster.u64 [%0], %1;"
                             :: "r"(ra), "l"(lov) : "memory");
            }
            asm volatile("barrier.cluster.arrive.aligned;" ::: "memory");
        } else {
            float* hr = hfin + (size_t)(r0 + r) * H_ + hc0 + c4;
            float* cr = cfin + (size_t)(r0 + r) * H_ + hc0 + c4;
            *(float4*)hr = make_float4(h4[0], h4[1], h4[2], h4[3]);
            *(float4*)cr = make_float4(creg[0], creg[1], creg[2], creg[3]);
        }
    }
}

extern "C" void kernel_launch(void* const* d_in, const int* in_sizes, int n_in,
                              void* d_out, int out_size)
{
    (void)in_sizes; (void)n_in; (void)out_size;
    const float* x   = (const float*)d_in[0];
    const float* h0  = (const float*)d_in[1];
    const float* c0  = (const float*)d_in[2];
    const float* Wi  = (const float*)d_in[3];
    const float* bi  = (const float*)d_in[4];
    const float* Wh  = (const float*)d_in[5];
    const float* bh  = (const float*)d_in[6];

    float* out     = (float*)d_out;
    float* outputs = out;
    float* hfin    = out + (size_t)T_ * B_ * H_;
    float* cfin    = hfin + (size_t)B_ * H_;

    float* pre;
    cudaGetSymbolAddress((void**)&pre, g_preact);

    cudaFuncSetAttribute(lstm_scan_cl, cudaFuncAttributeMaxDynamicSharedMemorySize,
                         SM_TOT);

    dim3 g1(8, T_);
    lstm_phase1<<<g1, 256>>>(x, Wi, bi, bh, pre);

    lstm_scan_cl<<<32, 256, SM_TOT>>>(h0, c0, Wh, pre, outputs, hfin, cfin);
}

// round 17
// speedup vs baseline: 2.5174x; 2.5174x over previous
#include <cuda_runtime.h>
#include <cuda_bf16.h>
#include <math.h>

#define T_ 128
#define B_ 128
#define I_ 256
#define H_ 256
#define G4_ 1024
#define NCTA 128

typedef unsigned long long u64;
typedef unsigned int u32;

__device__ float g_preact[(size_t)T_ * B_ * G4_];
__device__ unsigned g_slot[NCTA];

__device__ __forceinline__ unsigned ld_acq(const unsigned* p) {
    unsigned v;
    asm volatile("ld.acquire.gpu.global.u32 %0, [%1];" : "=r"(v) : "l"(p) : "memory");
    return v;
}
__device__ __forceinline__ void st_rel(unsigned* p, unsigned v) {
    asm volatile("st.release.gpu.global.u32 [%0], %1;" :: "l"(p), "r"(v) : "memory");
}
__device__ __forceinline__ u32 smem_u32(const void* p) {
    u32 a;
    asm("{ .reg .u64 t; cvta.to.shared.u64 t, %1; cvt.u32.u64 %0, t; }"
        : "=r"(a) : "l"(p));
    return a;
}
__device__ __forceinline__ u32 pack_bf16x2(float lo, float hi) {
    __nv_bfloat162 v = __halves2bfloat162(__float2bfloat16(lo), __float2bfloat16(hi));
    u32 r;
    memcpy(&r, &v, 4);
    return r;
}
// split f into hi bf16 (packed pairwise) + lo residual bf16
__device__ __forceinline__ void split2(float a, float b, u32& hw, u32& lw) {
    __nv_bfloat16 ba = __float2bfloat16(a);
    __nv_bfloat16 bb = __float2bfloat16(b);
    __nv_bfloat162 p = __halves2bfloat162(ba, bb);
    memcpy(&hw, &p, 4);
    lw = pack_bf16x2(a - __bfloat162float(ba), b - __bfloat162float(bb));
}

#define MMA_BF16(d0,d1,d2,d3,a0,a1,a2,a3,b0,b1)                              \
    asm volatile("mma.sync.aligned.m16n8k16.row.col.f32.bf16.bf16.f32 "      \
        "{%0,%1,%2,%3}, {%4,%5,%6,%7}, {%8,%9}, {%0,%1,%2,%3};"              \
        : "+f"(d0), "+f"(d1), "+f"(d2), "+f"(d3)                             \
        : "r"(a0), "r"(a1), "r"(a2), "r"(a3), "r"(b0), "r"(b1))

// ---------------------------------------------------------------------------
// Phase 1 via HMMA: preact[t] = x[t]@Wi[t] + bi + bh, bf16 hi/lo 3-pass.
// Grid (8 n-tiles, T), 256 thr. CTA tile: 128m x 128n, K=256 in 2 halves.
// X: row-major [m][k] (ldmatrix.x4 non-trans, R14-verified).
// W: native [k][n] (ldmatrix.x2.trans) -> conflict-free fills both.
// ---------------------------------------------------------------------------
#define ROWX 272                      // 136 bf16 per row (128 + 8 pad)
#define XPLANE (128 * ROWX)           // 34816 B
#define OFF_XHI 0
#define OFF_XLO (XPLANE)
#define OFF_WHI (2 * XPLANE)
#define OFF_WLO (3 * XPLANE)
#define OFF_BSM (4 * XPLANE)          // float[128]
#define SM_P1   (4 * XPLANE + 512)    // 139776 B

__global__ __launch_bounds__(256) void lstm_phase1_mma(
    const float* __restrict__ x, const float* __restrict__ Wi,
    const float* __restrict__ bi, const float* __restrict__ bh,
    float* __restrict__ preact)
{
    extern __shared__ char smc[];
    const u32 sb = smem_u32(smc);
    float* bsm = (float*)(smc + OFF_BSM);

    const int t = blockIdx.y, n0 = blockIdx.x * 128, tid = threadIdx.x;
    const int wid = tid >> 5, lane = tid & 31;
    const int mw = wid & 1;        // 2 m-groups of 4 m-tiles
    const int nw = wid >> 1;       // 4 n-groups of 4 n-tiles

    if (tid < 128)
        bsm[tid] = __ldg(bi + (size_t)t * G4_ + n0 + tid) +
                   __ldg(bh + (size_t)t * G4_ + n0 + tid);

    float d[4][4][4];
#pragma unroll
    for (int i = 0; i < 4; ++i)
#pragma unroll
        for (int j = 0; j < 4; ++j) {
            d[i][j][0] = 0.f; d[i][j][1] = 0.f; d[i][j][2] = 0.f; d[i][j][3] = 0.f;
        }

    for (int kh = 0; kh < 2; ++kh) {
        if (kh) __syncthreads();   // previous half's reads done before refill

        // ---- X fill: [128 m][128 k] bf16 hi/lo (coalesced float2 reads) ----
        {
            const float* xp = x + (size_t)t * B_ * I_ + kh * 128;
#pragma unroll
            for (int i = 0; i < 32; ++i) {
                const int s = i * 256 + tid;
                const int m = s >> 6, k2 = s & 63;
                float2 v = __ldg((const float2*)(xp + (size_t)m * I_ + k2 * 2));
                u32 hw, lw;
                split2(v.x, v.y, hw, lw);
                const u32 off = (u32)m * ROWX + (u32)k2 * 4;
                *(u32*)(smc + OFF_XHI + off) = hw;
                *(u32*)(smc + OFF_XLO + off) = lw;
            }
        }
        // ---- W fill: [128 k][128 n] bf16 hi/lo (native layout, coalesced) --
        {
            const float* wp = Wi + (size_t)t * I_ * G4_ + (size_t)kh * 128 * G4_ + n0;
#pragma unroll
            for (int i = 0; i < 16; ++i) {
                const int s = i * 256 + tid;
                const int k = s >> 5, q = s & 31;
                const int n4 = q * 4;
                float4 v = __ldg((const float4*)(wp + (size_t)k * G4_ + n4));
                u32 hw0, lw0, hw1, lw1;
                split2(v.x, v.y, hw0, lw0);
                split2(v.z, v.w, hw1, lw1);
                const u32 off = (u32)k * ROWX + (u32)n4 * 2;
                *(u32*)(smc + OFF_WHI + off)     = hw0;
                *(u32*)(smc + OFF_WHI + off + 4) = hw1;
                *(u32*)(smc + OFF_WLO + off)     = lw0;
                *(u32*)(smc + OFF_WLO + off + 4) = lw1;
            }
        }
        __syncthreads();

        // ---- MMA: warp covers (mw: 4 m-tiles) x (nw: 4 n-tiles), k half ----
#pragma unroll
        for (int kt = 0; kt < 8; ++kt) {
            u32 ah[4][4], al[4][4];
#pragma unroll
            for (int i = 0; i < 4; ++i) {
                const int m0 = (mw * 4 + i) * 16;
                const u32 aa = sb + OFF_XHI + (u32)(m0 + (lane & 15)) * ROWX +
                               (u32)kt * 32 + (u32)(lane >> 4) * 16;
                asm volatile("ldmatrix.sync.aligned.m8n8.x4.shared.b16 {%0,%1,%2,%3}, [%4];"
                    : "=r"(ah[i][0]), "=r"(ah[i][1]), "=r"(ah[i][2]), "=r"(ah[i][3])
                    : "r"(aa));
                asm volatile("ldmatrix.sync.aligned.m8n8.x4.shared.b16 {%0,%1,%2,%3}, [%4];"
                    : "=r"(al[i][0]), "=r"(al[i][1]), "=r"(al[i][2]), "=r"(al[i][3])
                    : "r"(aa + XPLANE));
            }
#pragma unroll
            for (int j = 0; j < 4; ++j) {
                const int nt = nw * 4 + j;
                const u32 bb = sb + OFF_WHI + (u32)(kt * 16 + (lane & 15)) * ROWX +
                               (u32)nt * 16;
                u32 bh0, bh1, bl0, bl1;
                asm volatile("ldmatrix.sync.aligned.m8n8.x2.trans.shared.b16 {%0,%1}, [%2];"
                    : "=r"(bh0), "=r"(bh1) : "r"(bb));
                asm volatile("ldmatrix.sync.aligned.m8n8.x2.trans.shared.b16 {%0,%1}, [%2];"
                    : "=r"(bl0), "=r"(bl1) : "r"(bb + XPLANE));
#pragma unroll
                for (int i = 0; i < 4; ++i) {
                    MMA_BF16(d[i][j][0], d[i][j][1], d[i][j][2], d[i][j][3],
                             ah[i][0], ah[i][1], ah[i][2], ah[i][3], bh0, bh1);
                    MMA_BF16(d[i][j][0], d[i][j][1], d[i][j][2], d[i][j][3],
                             ah[i][0], ah[i][1], ah[i][2], ah[i][3], bl0, bl1);
                    MMA_BF16(d[i][j][0], d[i][j][1], d[i][j][2], d[i][j][3],
                             al[i][0], al[i][1], al[i][2], al[i][3], bh0, bh1);
                }
            }
        }
    }

    // ---- store: + biases ----
    float* Cp = preact + (size_t)t * B_ * G4_ + n0;
#pragma unroll
    for (int i = 0; i < 4; ++i) {
#pragma unroll
        for (int j = 0; j < 4; ++j) {
            const int m = (mw * 4 + i) * 16 + (lane >> 2);
            const int n = (nw * 4 + j) * 8 + (lane & 3) * 2;
            const float2 bv = *(const float2*)&bsm[n];
            *(float2*)(Cp + (size_t)m * G4_ + n) =
                make_float2(d[i][j][0] + bv.x, d[i][j][1] + bv.y);
            *(float2*)(Cp + (size_t)(m + 8) * G4_ + n) =
                make_float2(d[i][j][2] + bv.x, d[i][j][3] + bv.y);
        }
    }
}

// ---------------------------------------------------------------------------
// Persistent scan — R8 byte-identical (best measured: 689.7us).
// ---------------------------------------------------------------------------
__global__ __launch_bounds__(256, 1) void lstm_scan(
    const float* __restrict__ h0, const float* __restrict__ c0,
    const float* __restrict__ Wh, const float* __restrict__ pre,
    float* __restrict__ outputs, float* __restrict__ hfin, float* __restrict__ cfin)
{
    extern __shared__ float smem[];
    float* Hs   = smem;                        // [256][33]
    float* Ws   = smem + 256 * 33;             // [256][32]
    float* gred = smem + 256 * 33 + 256 * 32;  // [4][32][36]
    float* gsm  = gred + 4 * 32 * 36;          // [32][33]

    const int tid = threadIdx.x;
    const int bid = blockIdx.x;
    const int cg = bid & 31, rg = bid >> 5;
    const int hc0 = cg * 8, r0 = rg * 32;

    const int r  = tid >> 3;
    const int c2 = tid & 7;
    const int oc0 = c2 * 4;
    const int g = oc0 >> 3;
    const int nbase = g * 256 + hc0 + (oc0 & 7);

    const int kg  = tid >> 6;
    const int wi2 = (tid & 63) >> 3;
    const int wj2 = tid & 7;
    const int kbase = kg * 64;

    const unsigned base = g_slot[bid];
    float creg = c0[(r0 + r) * H_ + hc0 + c2];

    for (int t = 0; t < T_; ++t) {
        const float* Wt = Wh + (size_t)t * H_ * G4_;
        const float* pt = pre + (size_t)t * B_ * G4_;

        float4 wv[8];
#pragma unroll
        for (int i = 0; i < 8; ++i) {
            const int s = i * 256 + tid;
            const int k = s >> 3, q = s & 7;
            const int gg = q >> 1, cc = (q & 1) * 4;
            wv[i] = __ldg((const float4*)(Wt + (size_t)k * G4_ + gg * 256 + hc0 + cc));
        }
        float4 pv = __ldg((const float4*)(pt + (size_t)(r0 + r) * G4_ + nbase));
#pragma unroll
        for (int i = 0; i < 8; ++i) {
            const int s = i * 256 + tid;
            const int k = s >> 3, q = s & 7;
            *(float4*)(Ws + k * 32 + q * 4) = wv[i];
        }

        if (t > 0) {
            if (tid < 32) {
                const unsigned tgt = base + (unsigned)t;
                const unsigned* sl = &g_slot[rg * 32 + tid];
                while (ld_acq(sl) < tgt) __nanosleep(32);
            }
        }
        __syncthreads();

        const float* hp = (t == 0) ? h0 : (outputs + (size_t)(t - 1) * B_ * H_);
#pragma unroll
        for (int a = 0; a < 4; ++a) {
            const int rr = (tid >> 5) + a * 8;
            const float* src = hp + (size_t)(r0 + rr) * H_;
            float* dst = Hs + rr;
#pragma unroll
            for (int b = 0; b < 8; ++b) {
                const int k = (tid & 31) + b * 32;
                dst[k * 33] = __ldcg(src + k);
            }
        }
        __syncthreads();

        u64 acc2[4][2];
#pragma unroll
        for (int e = 0; e < 4; ++e) { acc2[e][0] = 0ULL; acc2[e][1] = 0ULL; }
        {
            const float* hq = Hs + wi2 * 4;
            const float* wq = Ws + wj2 * 4;
#pragma unroll 4
            for (int k = 0; k < 64; ++k) {
                const int kk = kbase + k;
                const float* hrow = hq + kk * 33;
                const float h0v = hrow[0], h1v = hrow[1], h2v = hrow[2], h3v = hrow[3];
                ulonglong2 w2 = *(const ulonglong2*)(wq + kk * 32);
                u64 hd;
                asm("mov.b64 %0, {%1, %1};" : "=l"(hd) : "f"(h0v));
                asm("fma.rn.f32x2 %0, %1, %2, %0;" : "+l"(acc2[0][0]) : "l"(hd), "l"(w2.x));
                asm("fma.rn.f32x2 %0, %1, %2, %0;" : "+l"(acc2[0][1]) : "l"(hd), "l"(w2.y));
                asm("mov.b64 %0, {%1, %1};" : "=l"(hd) : "f"(h1v));
                asm("fma.rn.f32x2 %0, %1, %2, %0;" : "+l"(acc2[1][0]) : "l"(hd), "l"(w2.x));
                asm("fma.rn.f32x2 %0, %1, %2, %0;" : "+l"(acc2[1][1]) : "l"(hd), "l"(w2.y));
                asm("mov.b64 %0, {%1, %1};" : "=l"(hd) : "f"(h2v));
                asm("fma.rn.f32x2 %0, %1, %2, %0;" : "+l"(acc2[2][0]) : "l"(hd), "l"(w2.x));
                asm("fma.rn.f32x2 %0, %1, %2, %0;" : "+l"(acc2[2][1]) : "l"(hd), "l"(w2.y));
                asm("mov.b64 %0, {%1, %1};" : "=l"(hd) : "f"(h3v));
                asm("fma.rn.f32x2 %0, %1, %2, %0;" : "+l"(acc2[3][0]) : "l"(hd), "l"(w2.x));
                asm("fma.rn.f32x2 %0, %1, %2, %0;" : "+l"(acc2[3][1]) : "l"(hd), "l"(w2.y));
            }
        }

#pragma unroll
        for (int e = 0; e < 4; ++e) {
            float2 p0, p1;
            asm("mov.b64 {%0, %1}, %2;" : "=f"(p0.x), "=f"(p0.y) : "l"(acc2[e][0]));
            asm("mov.b64 {%0, %1}, %2;" : "=f"(p1.x), "=f"(p1.y) : "l"(acc2[e][1]));
            *(float4*)(gred + (size_t)(kg * 32 + wi2 * 4 + e) * 36 + wj2 * 4) =
                make_float4(p0.x, p0.y, p1.x, p1.y);
        }
        __syncthreads();

        {
            float4 s = make_float4(0.f, 0.f, 0.f, 0.f);
#pragma unroll
            for (int q = 0; q < 4; ++q) {
                float4 v = *(const float4*)(gred + (size_t)(q * 32 + r) * 36 + oc0);
                s.x += v.x; s.y += v.y; s.z += v.z; s.w += v.w;
            }
            gsm[r * 33 + oc0 + 0] = s.x + pv.x;
            gsm[r * 33 + oc0 + 1] = s.y + pv.y;
            gsm[r * 33 + oc0 + 2] = s.z + pv.z;
            gsm[r * 33 + oc0 + 3] = s.w + pv.w;
        }
        __syncthreads();

        {
            const float iv = gsm[r * 33 +  0 + c2];
            const float fv = gsm[r * 33 +  8 + c2];
            const float ov = gsm[r * 33 + 16 + c2];
            const float gv = gsm[r * 33 + 24 + c2];
            const float ig = 1.f / (1.f + expf(-iv));
            const float fg = 1.f / (1.f + expf(-fv));
            const float og = 1.f / (1.f + expf(-ov));
            const float gt = tanhf(gv);
            creg = fg * creg + ig * gt;
            const float hn = og * tanhf(creg);
            const int row = r0 + r, col = hc0 + c2;
            outputs[(size_t)t * B_ * H_ + row * H_ + col] = hn;
            if (t == T_ - 1) {
                hfin[row * H_ + col] = hn;
                cfin[row * H_ + col] = creg;
            }
        }

        __threadfence();
        __syncthreads();
        if (tid == 0) st_rel(&g_slot[bid], base + (unsigned)(t + 1));
    }
}

extern "C" void kernel_launch(void* const* d_in, const int* in_sizes, int n_in,
                              void* d_out, int out_size)
{
    (void)in_sizes; (void)n_in; (void)out_size;
    const float* x   = (const float*)d_in[0];
    const float* h0  = (const float*)d_in[1];
    const float* c0  = (const float*)d_in[2];
    const float* Wi  = (const float*)d_in[3];
    const float* bi  = (const float*)d_in[4];
    const float* Wh  = (const float*)d_in[5];
    const float* bh  = (const float*)d_in[6];

    float* out     = (float*)d_out;
    float* outputs = out;
    float* hfin    = out + (size_t)T_ * B_ * H_;
    float* cfin    = hfin + (size_t)B_ * H_;

    float* pre;
    cudaGetSymbolAddress((void**)&pre, g_preact);

    cudaFuncSetAttribute(lstm_phase1_mma,
                         cudaFuncAttributeMaxDynamicSharedMemorySize, SM_P1);
    const int smem_scan = (256 * 33 + 256 * 32 + 4 * 32 * 36 + 32 * 33) *
                          (int)sizeof(float);
    cudaFuncSetAttribute(lstm_scan,
                         cudaFuncAttributeMaxDynamicSharedMemorySize, smem_scan);

    dim3 g1(8, T_);
    lstm_phase1_mma<<<g1, 256, SM_P1>>>(x, Wi, bi, bh, pre);

    lstm_scan<<<NCTA, 256, smem_scan>>>(h0, c0, Wh, pre, outputs, hfin, cfin);
}